// round 3
// baseline (speedup 1.0000x reference)
#include <cuda_runtime.h>
#include <stdint.h>

#define Bn 4096
#define Dn 16
#define Mn 4
#define Rn 2048
#define Cn 10
#define BT 32
#define WARPS 16
#define THREADS (WARPS * 32)
#define RPW (Rn / WARPS)   // 128 rules per warp
#define EPSV 1e-9f

// 4 groups of 4 dims -> 256 entries each -> 1024 table entries x 32 lanes
#define TBL_ENTRIES 1024
#define CHUNK 16           // rules staged per transpose flush

// scratch (module-load allocation, allowed)
__device__ uint4 g_off[Rn];          // pre-scaled byte offsets into tbl
__device__ float g_cs[Rn * 12];      // folded consequents, padded to 12

__device__ __forceinline__ void ffma2(unsigned long long& acc,
                                      unsigned long long a,
                                      unsigned long long b) {
    asm("fma.rn.f32x2 %0, %1, %2, %0;" : "+l"(acc) : "l"(a), "l"(b));
}
__device__ __forceinline__ unsigned long long bcast2(float f) {
    unsigned long long r;
    asm("mov.b64 %0, {%1, %1};" : "=l"(r) : "f"(f));
    return r;
}

// ---------------------------------------------------------------------------
// prep: pack rule indices into pre-scaled table offsets; fold consequents
// ---------------------------------------------------------------------------
__global__ void anfis_prep(const float* __restrict__ cons,
                           const int*   __restrict__ rules) {
    int r = blockIdx.x * blockDim.x + threadIdx.x;
    if (r >= Rn) return;
    uint32_t p = 0;
#pragma unroll
    for (int d = 0; d < Dn; d++)
        p |= ((uint32_t)rules[r * Dn + d] & 3u) << (2 * d);
    uint4 o;
    o.x = ((p      ) & 255u) * 128u;            // group 0, bytes
    o.y = (256u + ((p >>  8) & 255u)) * 128u;   // group 1
    o.z = (512u + ((p >> 16) & 255u)) * 128u;   // group 2
    o.w = (768u + ((p >> 24) & 255u)) * 128u;   // group 3
    g_off[r] = o;

    float s[Cn];
#pragma unroll
    for (int c = 0; c < Cn; c++) s[c] = 0.f;
    const float* base = cons + (size_t)r * (Dn + 1) * Cn;
#pragma unroll
    for (int j = 0; j <= Dn; j++)
#pragma unroll
        for (int c = 0; c < Cn; c++) s[c] += base[j * Cn + c];
#pragma unroll
    for (int c = 0; c < Cn; c++) g_cs[r * 12 + c] = s[c];
    g_cs[r * 12 + 10] = 0.f;
    g_cs[r * 12 + 11] = 0.f;
}

// ---------------------------------------------------------------------------
// main: one CTA = 32 batch rows x all 2048 rules, 16 warps, two passes
// ---------------------------------------------------------------------------
// smem (floats):
//   tbl   [1024][32]   32768
//   mf    [64][32]      2048
//   pair  [8][16][32]   4096
//   xs    [32][16]       512
//   stage [W][16][34]   8704
//   wsum  [W][32]        512
//   wacc  [W][5][32]ull 5120 (float-equiv)
//   inv   [32], sx [32]   64
#define SMEM_FLOATS (32768 + 2048 + 4096 + 512 + WARPS*CHUNK*34 + WARPS*32 + WARPS*5*32*2 + 64)
#define SMEM_BYTES  (SMEM_FLOATS * 4)

__global__ void __launch_bounds__(THREADS, 1)
anfis_main(const float* __restrict__ x,
           const float* __restrict__ centers,
           const float* __restrict__ widths,
           float* __restrict__ out,     // (B, C)
           float* __restrict__ nf,      // (B, R)
           float* __restrict__ xext,    // (B, D+1)
           int write_aux) {
    extern __shared__ float sm[];
    float* tbl   = sm;                             // 1024*32
    float* mf    = tbl   + TBL_ENTRIES * 32;       // 64*32
    float* pair  = mf    + 64 * 32;                // 8*16*32
    float* xs    = pair  + 8 * 16 * 32;            // 32*16
    float* stage = xs    + 32 * 16;                // W*16*34
    float* wsum  = stage + WARPS * CHUNK * 34;     // W*32
    unsigned long long* wacc = (unsigned long long*)(wsum + WARPS * 32); // W*5*32
    float* inv_s = (float*)(wacc + WARPS * 5 * 32);
    float* sx    = inv_s + 32;

    const int tid  = threadIdx.x;
    const int w    = tid >> 5;
    const int lane = tid & 31;
    const int b0   = blockIdx.x * BT;

    // load x tile
    for (int i = tid; i < BT * Dn; i += THREADS)
        xs[i] = x[(size_t)b0 * Dn + i];
    __syncthreads();

    if (tid < BT) {
        float s = 1.f;
#pragma unroll
        for (int d = 0; d < Dn; d++) s += xs[tid * Dn + d];
        sx[tid] = s;
    }

    // membership values: mf[dm][b]
    for (int e = tid; e < 64 * 32; e += THREADS) {
        int dm = e >> 5, b = e & 31;
        int d = dm >> 2, m = dm & 3;
        float cc = centers[d * Mn + m];
        float ww = widths[d * Mn + m];
        float df = xs[b * Dn + d] - cc;
        mf[dm * 32 + b] = expf(-df * df / (2.f * ww * ww));
    }
    __syncthreads();

    // pair tables: pair[p][i2][b] = mf[2p][i2&3] * mf[2p+1][i2>>2]
    for (int pp = tid >> 5, i2 = 0; pp < 8 * 16; pp += WARPS) {
        int pr = pp >> 4; i2 = pp & 15;
        pair[pp * 32 + lane] =
            mf[((2 * pr)     * 4 + (i2 & 3))  * 32 + lane] *
            mf[((2 * pr + 1) * 4 + (i2 >> 2)) * 32 + lane];
    }
    __syncthreads();

    // 4-dim group tables from pairs
    for (int pp = w; pp < TBL_ENTRIES; pp += WARPS) {
        int g = pp >> 8, idx = pp & 255;
        tbl[pp * 32 + lane] =
            pair[((2 * g)     * 16 + (idx & 15))  * 32 + lane] *
            pair[((2 * g + 1) * 16 + (idx >> 4))  * 32 + lane];
    }
    __syncthreads();

    const char* tb = (const char*)tbl + lane * 4;
    const int rbase = w * RPW;

    // ---- pass 1: firing-strength sum only ----
    float fsum = 0.f;
#pragma unroll 8
    for (int rl = 0; rl < RPW; rl++) {
        const uint4 o = g_off[rbase + rl];
        float f0 = *(const float*)(tb + o.x);
        float f1 = *(const float*)(tb + o.y);
        float f2 = *(const float*)(tb + o.z);
        float f3 = *(const float*)(tb + o.w);
        fsum += (f0 * f1) * (f2 * f3);
    }
    wsum[w * 32 + lane] = fsum;
    __syncthreads();

    if (tid < BT) {
        float s = 0.f;
#pragma unroll
        for (int ww = 0; ww < WARPS; ww++) s += wsum[ww * 32 + tid];
        inv_s[tid] = 1.f / (s + EPSV);
    }
    __syncthreads();
    const float inv = inv_s[lane];

    // ---- pass 2: normalized fs -> nf, accumulate out ----
    const ulonglong2* cs2 = (const ulonglong2*)g_cs;   // 3 x ulonglong2 per rule
    unsigned long long a01 = 0, a23 = 0, a45 = 0, a67 = 0, a89 = 0;
    float* stg = stage + w * CHUNK * 34;

    for (int ch = 0; ch < RPW / CHUNK; ch++) {
        const int r0 = rbase + ch * CHUNK;
#pragma unroll 4
        for (int rl = 0; rl < CHUNK; rl++) {
            const int r = r0 + rl;
            const uint4 o = g_off[r];
            float f0 = *(const float*)(tb + o.x);
            float f1 = *(const float*)(tb + o.y);
            float f2 = *(const float*)(tb + o.z);
            float f3 = *(const float*)(tb + o.w);
            float fn = ((f0 * f1) * (f2 * f3)) * inv;
            stg[rl * 34 + lane] = fn;
            unsigned long long fp = bcast2(fn);
            ulonglong2 v0 = cs2[r * 3 + 0];
            ulonglong2 v1 = cs2[r * 3 + 1];
            ulonglong2 v2 = cs2[r * 3 + 2];
            ffma2(a01, fp, v0.x);
            ffma2(a23, fp, v0.y);
            ffma2(a45, fp, v1.x);
            ffma2(a67, fp, v1.y);
            ffma2(a89, fp, v2.x);
        }
        __syncwarp();
        if (write_aux) {
            // transposed, coalesced store of normalized fs
#pragma unroll
            for (int t = lane; t < CHUNK * 32; t += 32) {
                int b = t >> 4, rl2 = t & 15;
                nf[(size_t)(b0 + b) * Rn + r0 + rl2] = stg[rl2 * 34 + b];
            }
        }
        __syncwarp();
    }

    // cross-warp reduction of accumulators
    wacc[(w * 5 + 0) * 32 + lane] = a01;
    wacc[(w * 5 + 1) * 32 + lane] = a23;
    wacc[(w * 5 + 2) * 32 + lane] = a45;
    wacc[(w * 5 + 3) * 32 + lane] = a67;
    wacc[(w * 5 + 4) * 32 + lane] = a89;
    __syncthreads();

    const float* waccf = (const float*)wacc;
    for (int i = tid; i < BT * Cn; i += THREADS) {
        int c = i >> 5, b = i & 31;
        float a = 0.f;
#pragma unroll
        for (int ww = 0; ww < WARPS; ww++)
            a += waccf[(((ww * 5) + (c >> 1)) * 32 + b) * 2 + (c & 1)];
        out[(size_t)(b0 + b) * Cn + c] = sx[b] * a;
    }

    if (write_aux) {
        for (int i = tid; i < BT * (Dn + 1); i += THREADS) {
            int b = i / (Dn + 1), j = i % (Dn + 1);
            xext[(size_t)(b0 + b) * (Dn + 1) + j] = (j < Dn) ? xs[b * Dn + j] : 1.f;
        }
    }
}

// ---------------------------------------------------------------------------
extern "C" void kernel_launch(void* const* d_in, const int* in_sizes, int n_in,
                              void* d_out, int out_size) {
    const float* x       = (const float*)d_in[0];
    const float* centers = (const float*)d_in[1];
    const float* widths  = (const float*)d_in[2];
    const float* cons    = (const float*)d_in[3];
    const int*   rules   = (const int*)d_in[4];

    float* out = (float*)d_out;
    const long total = (long)Bn * Cn + (long)Bn * Rn + (long)Bn * (Dn + 1);
    const int write_aux = (out_size >= total) ? 1 : 0;
    float* nf   = out + (size_t)Bn * Cn;
    float* xext = nf + (size_t)Bn * Rn;

    anfis_prep<<<(Rn + 255) / 256, 256>>>(cons, rules);

    cudaFuncSetAttribute(anfis_main, cudaFuncAttributeMaxDynamicSharedMemorySize,
                         SMEM_BYTES);
    anfis_main<<<Bn / BT, THREADS, SMEM_BYTES>>>(x, centers, widths,
                                                 out, nf, xext, write_aux);
}

// round 4
// speedup vs baseline: 1.1929x; 1.1929x over previous
#include <cuda_runtime.h>
#include <stdint.h>

#define Bn 4096
#define Dn 16
#define Mn 4
#define Rn 2048
#define Cn 10
#define BT 32
#define WARPS 16
#define THREADS 512
#define HALF_R 1024
#define RPW 64        // rules per warp (HALF_R / WARPS)
#define RPW_A 32      // staged in smem
#define RPW_B 32      // held in registers
#define EPSV 1e-9f

// scratch (module-load allocation, allowed)
__device__ uint4 g_off[Rn];       // pre-scaled byte offsets into tbl
__device__ float g_cs[Rn * 12];   // folded consequents, padded to 12

__device__ __forceinline__ void ffma2(unsigned long long& acc,
                                      unsigned long long a,
                                      unsigned long long b) {
    asm("fma.rn.f32x2 %0, %1, %2, %0;" : "+l"(acc) : "l"(a), "l"(b));
}
__device__ __forceinline__ unsigned long long bcast2(float f) {
    unsigned long long r;
    asm("mov.b64 %0, {%1, %1};" : "=l"(r) : "f"(f));
    return r;
}
__device__ __forceinline__ uint32_t ctarank() {
    uint32_t r; asm("mov.u32 %0, %%cluster_ctarank;" : "=r"(r)); return r;
}
__device__ __forceinline__ float dsmem_ld(uint32_t local_addr, uint32_t rank) {
    uint32_t ra; float v;
    asm("mapa.shared::cluster.u32 %0, %1, %2;" : "=r"(ra) : "r"(local_addr), "r"(rank));
    asm volatile("ld.shared::cluster.f32 %0, [%1];" : "=f"(v) : "r"(ra));
    return v;
}
#define CLUSTER_SYNC() do { \
    asm volatile("barrier.cluster.arrive.aligned;" ::: "memory"); \
    asm volatile("barrier.cluster.wait.aligned;" ::: "memory"); } while (0)

// ---------------------------------------------------------------------------
// prep: coalesced fold of consequents + rule packing (8 rules per 256-thr CTA)
// ---------------------------------------------------------------------------
__global__ void anfis_prep(const float* __restrict__ cons,
                           const int*   __restrict__ rules) {
    __shared__ float s[8 * 170];
    const int r0 = blockIdx.x * 8;
    const float* base = cons + (size_t)r0 * 170;
    for (int i = threadIdx.x; i < 8 * 170; i += 256) s[i] = base[i];
    __syncthreads();
    const int t = threadIdx.x;
    if (t < 80) {
        int rr = t / 10, c = t % 10;
        float a = 0.f;
#pragma unroll
        for (int j = 0; j < 17; j++) a += s[rr * 170 + j * 10 + c];
        g_cs[(size_t)(r0 + rr) * 12 + c] = a;
    } else if (t < 96) {
        int rr = (t - 80) >> 1;
        g_cs[(size_t)(r0 + rr) * 12 + 10 + ((t - 80) & 1)] = 0.f;
    } else if (t < 104) {
        int rr = t - 96;
        const int* rp = rules + (size_t)(r0 + rr) * Dn;
        uint32_t p = 0;
#pragma unroll
        for (int d = 0; d < Dn; d++)
            p |= ((uint32_t)rp[d] & 3u) << (2 * d);
        uint4 o;
        o.x = ((p      ) & 255u) * 128u;
        o.y = (256u + ((p >>  8) & 255u)) * 128u;
        o.z = (512u + ((p >> 16) & 255u)) * 128u;
        o.w = (768u + ((p >> 24) & 255u)) * 128u;
        g_off[r0 + rr] = o;
    }
}

// ---------------------------------------------------------------------------
// main: cluster of 2 CTAs per batch tile; each CTA = 32 rows x 1024 rules
// ---------------------------------------------------------------------------
// smem floats: tbl 32768 | stage 16896 (overlays mf 2048 + pair 4096 in build)
//              xs 512 | red_sum 32 | red_acc 320 | inv 32 | sx 32
#define STAGE_FLOATS (WARPS * RPW_A * 33)
#define SMEM_FLOATS  (32768 + STAGE_FLOATS + 512 + 32 + 320 + 32 + 32)
#define SMEM_BYTES   (SMEM_FLOATS * 4)

__global__ void __launch_bounds__(THREADS, 1) __cluster_dims__(2, 1, 1)
anfis_main(const float* __restrict__ x,
           const float* __restrict__ centers,
           const float* __restrict__ widths,
           float* __restrict__ out,     // (B, C)
           float* __restrict__ nf,      // (B, R)
           float* __restrict__ xext,    // (B, D+1)
           int write_aux) {
    extern __shared__ float sm[];
    float* tbl     = sm;                       // 1024*32
    float* stage   = tbl + 32768;              // 16*32*33
    float* xs      = stage + STAGE_FLOATS;     // 32*16
    float* red_sum = xs + 512;                 // 32
    float* red_acc = red_sum + 32;             // 10*32
    float* inv_s   = red_acc + 320;            // 32
    float* sx      = inv_s + 32;               // 32
    float* mf      = stage;                    // overlay (build phase only)
    float* pair    = stage + 2048;             // overlay (build phase only)

    const int tid  = threadIdx.x;
    const int w    = tid >> 5;
    const int lane = tid & 31;
    const uint32_t rank = ctarank();
    const uint32_t peer = rank ^ 1u;
    const int tile = blockIdx.x >> 1;
    const int b0   = tile * BT;

    // ---- build phase ----
    for (int i = tid; i < BT * Dn; i += THREADS)
        xs[i] = x[(size_t)b0 * Dn + i];
    for (int i = tid; i < 352; i += THREADS)
        red_sum[i] = 0.f;   // red_sum + red_acc (contiguous)
    __syncthreads();

    if (tid < BT) {
        float s = 1.f;
#pragma unroll
        for (int d = 0; d < Dn; d++) s += xs[tid * Dn + d];
        sx[tid] = s;
    }

    for (int e = tid; e < 64 * 32; e += THREADS) {
        int dm = e >> 5, b = e & 31;
        int d = dm >> 2, m = dm & 3;
        float cc = centers[d * Mn + m];
        float ww = widths[d * Mn + m];
        float df = xs[b * Dn + d] - cc;
        mf[dm * 32 + b] = expf(-df * df / (2.f * ww * ww));
    }
    __syncthreads();

    for (int pp = w; pp < 8 * 16; pp += WARPS) {
        int pr = pp >> 4, i2 = pp & 15;
        pair[pp * 32 + lane] =
            mf[((2 * pr)     * 4 + (i2 & 3))  * 32 + lane] *
            mf[((2 * pr + 1) * 4 + (i2 >> 2)) * 32 + lane];
    }
    __syncthreads();

    for (int pp = w; pp < 1024; pp += WARPS) {
        int g = pp >> 8, idx = pp & 255;
        tbl[pp * 32 + lane] =
            pair[((2 * g)     * 16 + (idx & 15)) * 32 + lane] *
            pair[((2 * g + 1) * 16 + (idx >> 4)) * 32 + lane];
    }
    __syncthreads();   // stage region free from here

    // ---- compute: 64 rules/warp, 32 staged + 32 in registers ----
    const char* tb = (const char*)tbl + lane * 4;
    const ulonglong2* cs2 = (const ulonglong2*)g_cs;
    const int rbase = (int)rank * HALF_R + w * RPW;
    float* stg = stage + w * (RPW_A * 33);

    float fsum = 0.f;
    unsigned long long a01 = 0, a23 = 0, a45 = 0, a67 = 0, a89 = 0;

#pragma unroll 8
    for (int rl = 0; rl < RPW_A; rl++) {
        const int r = rbase + rl;
        const uint4 o = g_off[r];
        float f0 = *(const float*)(tb + o.x);
        float f1 = *(const float*)(tb + o.y);
        float f2 = *(const float*)(tb + o.z);
        float f3 = *(const float*)(tb + o.w);
        float f = (f0 * f1) * (f2 * f3);
        stg[rl * 33 + lane] = f;
        fsum += f;
        unsigned long long fp = bcast2(f);
        ulonglong2 v0 = cs2[r * 3 + 0];
        ulonglong2 v1 = cs2[r * 3 + 1];
        ulonglong2 v2 = cs2[r * 3 + 2];
        ffma2(a01, fp, v0.x); ffma2(a23, fp, v0.y);
        ffma2(a45, fp, v1.x); ffma2(a67, fp, v1.y);
        ffma2(a89, fp, v2.x);
    }

    float fB[RPW_B];
#pragma unroll
    for (int rl = 0; rl < RPW_B; rl++) {
        const int r = rbase + RPW_A + rl;
        const uint4 o = g_off[r];
        float f0 = *(const float*)(tb + o.x);
        float f1 = *(const float*)(tb + o.y);
        float f2 = *(const float*)(tb + o.z);
        float f3 = *(const float*)(tb + o.w);
        float f = (f0 * f1) * (f2 * f3);
        fB[rl] = f;
        fsum += f;
        unsigned long long fp = bcast2(f);
        ulonglong2 v0 = cs2[r * 3 + 0];
        ulonglong2 v1 = cs2[r * 3 + 1];
        ulonglong2 v2 = cs2[r * 3 + 2];
        ffma2(a01, fp, v0.x); ffma2(a23, fp, v0.y);
        ffma2(a45, fp, v1.x); ffma2(a67, fp, v1.y);
        ffma2(a89, fp, v2.x);
    }

    // ---- CTA-local reduction (atomics into smem) ----
    atomicAdd(&red_sum[lane], fsum);
    {
        union { unsigned long long u; float2 f; } c0, c1, c2, c3, c4;
        c0.u = a01; c1.u = a23; c2.u = a45; c3.u = a67; c4.u = a89;
        atomicAdd(&red_acc[0 * 32 + lane], c0.f.x);
        atomicAdd(&red_acc[1 * 32 + lane], c0.f.y);
        atomicAdd(&red_acc[2 * 32 + lane], c1.f.x);
        atomicAdd(&red_acc[3 * 32 + lane], c1.f.y);
        atomicAdd(&red_acc[4 * 32 + lane], c2.f.x);
        atomicAdd(&red_acc[5 * 32 + lane], c2.f.y);
        atomicAdd(&red_acc[6 * 32 + lane], c3.f.x);
        atomicAdd(&red_acc[7 * 32 + lane], c3.f.y);
        atomicAdd(&red_acc[8 * 32 + lane], c4.f.x);
        atomicAdd(&red_acc[9 * 32 + lane], c4.f.y);
    }
    __syncthreads();

    // ---- cross-CTA exchange (DSMEM) ----
    CLUSTER_SYNC();
    if (tid < 32) {
        uint32_t la = (uint32_t)__cvta_generic_to_shared(&red_sum[tid]);
        float ps = dsmem_ld(la, peer);
        inv_s[tid] = 1.f / (red_sum[tid] + ps + EPSV);
    }
    __syncthreads();

    // ---- outputs ----
    if (rank == 0) {
        for (int i = tid; i < BT * Cn; i += THREADS) {
            uint32_t la = (uint32_t)__cvta_generic_to_shared(&red_acc[i]);
            float pa = dsmem_ld(la, peer);
            int c = i >> 5, b = i & 31;
            out[(size_t)(b0 + b) * Cn + c] = sx[b] * inv_s[b] * (red_acc[i] + pa);
        }
        if (write_aux) {
            for (int i = tid; i < BT * (Dn + 1); i += THREADS) {
                int b = i / (Dn + 1), j = i % (Dn + 1);
                xext[(size_t)(b0 + b) * (Dn + 1) + j] = (j < Dn) ? xs[b * Dn + j] : 1.f;
            }
        }
    }

    if (write_aux) {
        // flush A (staged raw f), normalized on the way out
#pragma unroll 4
        for (int rr = 0; rr < BT; rr++)
            nf[(size_t)(b0 + rr) * Rn + rbase + lane] = stg[lane * 33 + rr] * inv_s[rr];
        __syncwarp();
        // stage + flush B (register-held raw f)
#pragma unroll
        for (int i = 0; i < RPW_B; i++)
            stg[i * 33 + lane] = fB[i];
        __syncwarp();
#pragma unroll 4
        for (int rr = 0; rr < BT; rr++)
            nf[(size_t)(b0 + rr) * Rn + rbase + RPW_A + lane] = stg[lane * 33 + rr] * inv_s[rr];
    }

    CLUSTER_SYNC();   // keep smem alive until peer finished reading
}

// ---------------------------------------------------------------------------
extern "C" void kernel_launch(void* const* d_in, const int* in_sizes, int n_in,
                              void* d_out, int out_size) {
    const float* x       = (const float*)d_in[0];
    const float* centers = (const float*)d_in[1];
    const float* widths  = (const float*)d_in[2];
    const float* cons    = (const float*)d_in[3];
    const int*   rules   = (const int*)d_in[4];

    float* out = (float*)d_out;
    const long total = (long)Bn * Cn + (long)Bn * Rn + (long)Bn * (Dn + 1);
    const int write_aux = (out_size >= total) ? 1 : 0;
    float* nf   = out + (size_t)Bn * Cn;
    float* xext = nf + (size_t)Bn * Rn;

    anfis_prep<<<Rn / 8, 256>>>(cons, rules);

    cudaFuncSetAttribute(anfis_main, cudaFuncAttributeMaxDynamicSharedMemorySize,
                         SMEM_BYTES);
    anfis_main<<<(Bn / BT) * 2, THREADS, SMEM_BYTES>>>(x, centers, widths,
                                                       out, nf, xext, write_aux);
}